// round 12
// baseline (speedup 1.0000x reference)
#include <cuda_runtime.h>
#include <cuda_bf16.h>
#include <mma.h>
#include <stdint.h>

using namespace nvcuda;

#define N_TOK 32768
#define DIM   512
#define KCB   1024

#define DECAY 0.99f
#define OMD   0.01f
#define EPS_C 1e-5f
#define MARGIN 0.15f   // ~40 sigma of bf16 score error
#define SLOTS 12

// ---------------- scratch (no allocations allowed) ----------------
__device__ float g_c2[KCB];
__device__ float g_z2[N_TOK];
__device__ int   g_idx[N_TOK];
__device__ float g_counts[KCB];
__device__ float g_sums[KCB * DIM];
__device__ float g_newcs[KCB];
__device__ float g_ntot;
__device__ float g_norm[KCB * DIM];
__device__ __align__(16) __nv_bfloat16 g_zh[N_TOK * (size_t)DIM];
__device__ __align__(16) __nv_bfloat16 g_cbh[KCB * DIM];

// ---------------- zero accumulators ----------------
__global__ void zero_kernel() {
    int t = blockIdx.x * blockDim.x + threadIdx.x;
    int stride = gridDim.x * blockDim.x;
    for (int i = t; i < KCB * DIM; i += stride) g_sums[i] = 0.0f;
    if (t < KCB) g_counts[t] = 0.0f;
}

// ---------------- c2/z2 + fused bf16 conversion ----------------
__global__ void c2_kernel(const float* __restrict__ cb) {
    int k = blockIdx.x, t = threadIdx.x;  // 128 threads
    float4 v = ((const float4*)(cb + (size_t)k * DIM))[t];
    union { __nv_bfloat162 h[2]; uint2 u; } cv;
    cv.h[0] = __floats2bfloat162_rn(v.x, v.y);
    cv.h[1] = __floats2bfloat162_rn(v.z, v.w);
    ((uint2*)(g_cbh + (size_t)k * DIM))[t] = cv.u;
    float s = v.x * v.x + v.y * v.y + v.z * v.z + v.w * v.w;
    #pragma unroll
    for (int o = 16; o > 0; o >>= 1) s += __shfl_down_sync(0xffffffffu, s, o);
    __shared__ float ws[4];
    if ((t & 31) == 0) ws[t >> 5] = s;
    __syncthreads();
    if (t == 0) g_c2[k] = ws[0] + ws[1] + ws[2] + ws[3];
}

__global__ void z2_kernel(const float* __restrict__ z) {
    int r = blockIdx.x, t = threadIdx.x;  // 128 threads
    float4 v = ((const float4*)(z + (size_t)r * DIM))[t];
    union { __nv_bfloat162 h[2]; uint2 u; } cv;
    cv.h[0] = __floats2bfloat162_rn(v.x, v.y);
    cv.h[1] = __floats2bfloat162_rn(v.z, v.w);
    ((uint2*)(g_zh + (size_t)r * DIM))[t] = cv.u;
    float s = v.x * v.x + v.y * v.y + v.z * v.z + v.w * v.w;
    #pragma unroll
    for (int o = 16; o > 0; o >>= 1) s += __shfl_down_sync(0xffffffffu, s, o);
    __shared__ float ws[4];
    if ((t & 31) == 0) ws[t >> 5] = s;
    __syncthreads();
    if (t == 0) g_z2[r] = ws[0] + ws[1] + ws[2] + ws[3];
}

// ---------------- fused HMMA GEMM + candidate select + exact rerank ------
// Per CTA: 128 rows, all 1024 codes (8 chunks of 128). Approx scores stay in
// smem; per-row running min + candidate slots collected per chunk (threshold
// monotonically shrinks -> collected set is a superset of the final margin
// set). After all chunks: per-row EXACT fp32 rerank of surviving candidates
// with the reference-exact arithmetic (sequential ascending-d FMA chain,
// fl(fl(z2-2dot)+c2), ascending-code order + strict '<' == lowest-index
// tie-break) — identical formula to the R4/R7 passing kernels.
#define PAW 72     // A/B smem pitch in bf16 (64 data + 8 pad)
#define PCW 132    // C smem pitch in f32 (128 rows + 4 pad)
#define OFF_A    0
#define OFF_B    18432
#define OFF_C    36864
#define OFF_C2   104448
#define OFF_MIN  104960
#define OFF_CNT  105472
#define OFF_CC   105984                    // cand codes [128][SLOTS]
#define OFF_CS   (OFF_CC + 128*SLOTS*4)    // cand scores [128][SLOTS]
#define OFF_OFL  (OFF_CS + 128*SLOTS*4)    // overflow count + row list
#define GSM_SIZE (OFF_OFL + 4 + 128*4 + 16)

__global__ __launch_bounds__(256)
void gemm_kernel(const float* __restrict__ z, const float* __restrict__ cb) {
    extern __shared__ __align__(16) unsigned char sm[];
    __nv_bfloat16* As = (__nv_bfloat16*)(sm + OFF_A);   // [128][PAW]
    __nv_bfloat16* Bs = (__nv_bfloat16*)(sm + OFF_B);   // [128][PAW]
    float* Cs   = (float*)(sm + OFF_C);                 // [128 codes][PCW]
    float* c2s  = (float*)(sm + OFF_C2);                // [128]
    float* rmin = (float*)(sm + OFF_MIN);               // [128]
    int*   rcnt = (int*)(sm + OFF_CNT);                 // [128]
    int*   cc   = (int*)(sm + OFF_CC);                  // [128][SLOTS]
    float* cs   = (float*)(sm + OFF_CS);                // [128][SLOTS]
    int*   ofl  = (int*)(sm + OFF_OFL);                 // [0]=count, rows...

    const int tid = threadIdx.x;
    const int wid = tid >> 5;
    const int wr = wid & 3;    // row group: rows wr*32
    const int wc = wid >> 2;   // col group: codes wc*64
    const int rb = blockIdx.x * 128;

    if (tid < 128) { rmin[tid] = 3.4e38f; rcnt[tid] = 0; }
    if (tid == 0) ofl[0] = 0;

    wmma::fragment<wmma::matrix_a, 16, 16, 16, __nv_bfloat16, wmma::row_major> af[2];
    wmma::fragment<wmma::matrix_b, 16, 16, 16, __nv_bfloat16, wmma::col_major> bf[4];
    wmma::fragment<wmma::accumulator, 16, 16, 16, float> acc[2][4];

    for (int ch = 0; ch < 8; ch++) {
        if (tid < 128) c2s[tid] = g_c2[ch * 128 + tid];
        #pragma unroll
        for (int f = 0; f < 2; f++)
            #pragma unroll
            for (int g = 0; g < 4; g++)
                wmma::fill_fragment(acc[f][g], 0.0f);

        for (int slab = 0; slab < 8; slab++) {
            #pragma unroll
            for (int i = 0; i < 4; i++) {
                int idx = i * 256 + tid;           // 0..1023
                int r = idx >> 3, grp = idx & 7;
                *(uint4*)(As + r * PAW + grp * 8) =
                    *(const uint4*)(g_zh + (size_t)(rb + r) * DIM + slab * 64 + grp * 8);
            }
            #pragma unroll
            for (int i = 0; i < 4; i++) {
                int idx = i * 256 + tid;
                int n = idx >> 3, grp = idx & 7;
                *(uint4*)(Bs + n * PAW + grp * 8) =
                    *(const uint4*)(g_cbh + (size_t)(ch * 128 + n) * DIM + slab * 64 + grp * 8);
            }
            __syncthreads();

            #pragma unroll
            for (int ks = 0; ks < 4; ks++) {
                #pragma unroll
                for (int f = 0; f < 2; f++)
                    wmma::load_matrix_sync(af[f],
                        As + (wr * 32 + f * 16) * PAW + ks * 16, PAW);
                #pragma unroll
                for (int g = 0; g < 4; g++)
                    wmma::load_matrix_sync(bf[g],
                        Bs + (wc * 64 + g * 16) * PAW + ks * 16, PAW);
                #pragma unroll
                for (int f = 0; f < 2; f++)
                    #pragma unroll
                    for (int g = 0; g < 4; g++)
                        wmma::mma_sync(acc[f][g], af[f], bf[g], acc[f][g]);
            }
            __syncthreads();
        }

        // scores to smem, col-major: (row r, code c) -> Cs[c*PCW + r]
        #pragma unroll
        for (int f = 0; f < 2; f++)
            #pragma unroll
            for (int g = 0; g < 4; g++)
                wmma::store_matrix_sync(
                    Cs + (wc * 64 + g * 16) * PCW + wr * 32 + f * 16,
                    acc[f][g], PCW, wmma::mem_col_major);
        __syncthreads();

        // per-row chunk scan: min merge + candidate collection
        if (tid < 128) {
            int r = tid;
            float rm = rmin[r];
            float m = 3.4e38f;
            #pragma unroll 8
            for (int c = 0; c < 128; c++)
                m = fminf(m, fmaf(-2.0f, Cs[c * PCW + r], c2s[c]));
            rm = fminf(rm, m);
            float thr = rm + MARGIN;
            int cnt = rcnt[r];
            for (int c = 0; c < 128; c++) {
                float sc = fmaf(-2.0f, Cs[c * PCW + r], c2s[c]);
                if (sc <= thr) {
                    if (cnt < SLOTS) {
                        cc[r * SLOTS + cnt] = ch * 128 + c;
                        cs[r * SLOTS + cnt] = sc;
                    }
                    cnt++;
                }
            }
            rcnt[r] = cnt;
            rmin[r] = rm;
        }
        __syncthreads();
    }

    // ---- exact rerank (per row, its own thread) ----
    if (tid < 128) {
        int r = tid;
        int cnt = rcnt[r];
        if (cnt <= SLOTS) {
            float thr = rmin[r] + MARGIN;
            float z2v = g_z2[rb + r];
            const float* zr = z + (size_t)(rb + r) * DIM;
            float best = 3.4e38f;
            int bi = 0;
            for (int i = 0; i < cnt; i++) {
                if (cs[r * SLOTS + i] > thr) continue;  // final-threshold filter
                int code = cc[r * SLOTS + i];
                const float* cr = cb + (size_t)code * DIM;
                float dot = 0.0f;
                #pragma unroll 8
                for (int d = 0; d < DIM; d++) dot = fmaf(zr[d], cr[d], dot);
                float t = fmaf(-2.0f, dot, z2v);
                float sc = __fadd_rn(t, g_c2[code]);
                if (sc < best) { best = sc; bi = code; }
            }
            g_idx[rb + r] = bi;
        } else {
            int slot = atomicAdd(&ofl[0], 1);
            ofl[1 + slot] = r;
        }
    }
    __syncthreads();

    // ---- overflow fallback (prob ~0): block-cooperative exact full scan ----
    int novl = ofl[0];
    for (int i = 0; i < novl; i++) {
        int r = ofl[1 + i];
        float z2v = g_z2[rb + r];
        const float* zr = z + (size_t)(rb + r) * DIM;
        unsigned long long mykey = ~0ull;
        for (int code = tid; code < KCB; code += 256) {
            const float* cr = cb + (size_t)code * DIM;
            float dot = 0.0f;
            #pragma unroll 8
            for (int d = 0; d < DIM; d++) dot = fmaf(zr[d], cr[d], dot);
            float t = fmaf(-2.0f, dot, z2v);
            float sc = __fadd_rn(t, g_c2[code]);
            unsigned b = __float_as_uint(sc);
            b = (b & 0x80000000u) ? ~b : (b | 0x80000000u);
            unsigned long long key = ((unsigned long long)b << 32) | (unsigned)code;
            if (key < mykey) mykey = key;
        }
        unsigned long long* kred = (unsigned long long*)Cs;
        kred[tid] = mykey;
        __syncthreads();
        if (tid == 0) {
            unsigned long long m = kred[0];
            for (int x = 1; x < 256; x++) if (kred[x] < m) m = kred[x];
            g_idx[rb + r] = (int)(m & 0xffffffffull);
        }
        __syncthreads();
    }
}

// ---------------- scatter: counts[k] += 1, sums[k] += z_n ----------------
__global__ void scatter_kernel(const float* __restrict__ z) {
    int g = blockIdx.x * blockDim.x + threadIdx.x;
    int row = g >> 5;
    int lane = g & 31;
    if (row >= N_TOK) return;
    int k = g_idx[row];
    const float4* zr = (const float4*)(z + (size_t)row * DIM);
    float* dst = g_sums + (size_t)k * DIM;
    #pragma unroll
    for (int i = 0; i < 4; i++) {
        int e = lane + i * 32;
        float4 v = zr[e];
        atomicAdd(dst + 4 * e + 0, v.x);
        atomicAdd(dst + 4 * e + 1, v.y);
        atomicAdd(dst + 4 * e + 2, v.z);
        atomicAdd(dst + 4 * e + 3, v.w);
    }
    if (lane == 0) atomicAdd(&g_counts[k], 1.0f);
}

// ---------------- EMA cluster sizes + total n ----------------
__global__ void newcs_kernel(const float* __restrict__ ema_cs) {
    __shared__ float red[1024];
    int t = threadIdx.x;  // 1024 threads
    float v = DECAY * ema_cs[t] + OMD * g_counts[t];
    g_newcs[t] = v;
    red[t] = v;
    __syncthreads();
    for (int s = 512; s > 0; s >>= 1) {
        if (t < s) red[t] += red[t + s];
        __syncthreads();
    }
    if (t == 0) g_ntot = red[0];
}

// ---------------- normalized codebook ----------------
__global__ void norm_kernel(const float* __restrict__ ema_w) {
    int k = blockIdx.x;
    int t = threadIdx.x;  // 128 threads
    float n = g_ntot;
    float cs = g_newcs[k];
    float smoothed = (cs + EPS_C) / (n + (float)KCB * EPS_C) * n;
    float inv = 1.0f / smoothed;
    const float4* w = (const float4*)(ema_w + (size_t)k * DIM);
    const float4* s = (const float4*)(g_sums + (size_t)k * DIM);
    float4* o = (float4*)(g_norm + (size_t)k * DIM);
    float4 wv = w[t], sv = s[t], ov;
    ov.x = (DECAY * wv.x + OMD * sv.x) * inv;
    ov.y = (DECAY * wv.y + OMD * sv.y) * inv;
    ov.z = (DECAY * wv.z + OMD * sv.z) * inv;
    ov.w = (DECAY * wv.w + OMD * sv.w) * inv;
    o[t] = ov;
}

// ---------------- gather + emit outputs ----------------
__global__ void out_kernel(const float* __restrict__ z,
                           float* __restrict__ idx_out,
                           float* __restrict__ q_out,
                           float* __restrict__ st_out) {
    int row = blockIdx.x;
    int t = threadIdx.x;  // 128 threads
    int k = g_idx[row];
    const float4* nr = (const float4*)(g_norm + (size_t)k * DIM);
    float4 qv = nr[t];
    if (q_out)
        ((float4*)(q_out + (size_t)row * DIM))[t] = qv;
    if (st_out) {
        const float4* zr = (const float4*)(z + (size_t)row * DIM);
        float4 zv = zr[t];
        float4 sv;
        sv.x = zv.x + (qv.x - zv.x);
        sv.y = zv.y + (qv.y - zv.y);
        sv.z = zv.z + (qv.z - zv.z);
        sv.w = zv.w + (qv.w - zv.w);
        ((float4*)(st_out + (size_t)row * DIM))[t] = sv;
    }
    if (idx_out && t == 0) idx_out[row] = (float)k;
}

// ---------------- host launcher ----------------
extern "C" void kernel_launch(void* const* d_in, const int* in_sizes, int n_in,
                              void* d_out, int out_size) {
    const float* z   = (const float*)d_in[0];
    const float* cb  = (const float*)d_in[1];
    const float* ecs = (const float*)d_in[2];
    const float* ew  = (const float*)d_in[3];
    float* out = (float*)d_out;

    static bool attr_set = false;
    if (!attr_set) {
        cudaFuncSetAttribute(gemm_kernel,
                             cudaFuncAttributeMaxDynamicSharedMemorySize,
                             GSM_SIZE);
        attr_set = true;
    }

    zero_kernel<<<512, 256>>>();
    c2_kernel<<<KCB, 128>>>(cb);
    z2_kernel<<<N_TOK, 128>>>(z);
    gemm_kernel<<<N_TOK / 128, 256, GSM_SIZE>>>(z, cb);
    scatter_kernel<<<(N_TOK * 32) / 256, 256>>>(z);
    newcs_kernel<<<1, 1024>>>(ecs);
    norm_kernel<<<KCB, 128>>>(ew);

    const long long N = N_TOK, D = DIM;
    const long long os = out_size;
    float *idxp = nullptr, *qp = nullptr, *stp = nullptr;
    if (os == N * (2 * D + 1)) {            // [idx, q, q_st]
        idxp = out; qp = out + N; stp = out + N + N * D;
    } else if (os == N * 2 * D) {           // [q, q_st]
        qp = out; stp = out + N * D;
    } else if (os == N * D) {               // [q]
        qp = out;
    } else if (os == N) {                   // [idx]
        idxp = out;
    } else {
        idxp = out;
        if (os >= N + N * D) qp = out + N;
        if (os >= N + 2 * N * D) stp = out + N + N * D;
    }
    out_kernel<<<N_TOK, 128>>>(z, idxp, qp, stp);
}

// round 13
// speedup vs baseline: 1.1119x; 1.1119x over previous
#include <cuda_runtime.h>
#include <cuda_bf16.h>
#include <mma.h>
#include <stdint.h>

using namespace nvcuda;

#define N_TOK 32768
#define DIM   512
#define KCB   1024

#define DECAY 0.99f
#define OMD   0.01f
#define EPS_C 1e-5f
#define MARGIN 0.15f   // ~40 sigma of bf16 score error
#define SLOTS 12

// ---------------- scratch (no allocations allowed) ----------------
__device__ float g_c2[KCB];
__device__ float g_z2[N_TOK];
__device__ int   g_idx[N_TOK];
__device__ float g_counts[KCB];
__device__ float g_sums[KCB * DIM];
__device__ float g_newcs[KCB];
__device__ float g_ntot;
__device__ float g_norm[KCB * DIM];
__device__ __align__(16) __nv_bfloat16 g_zh[N_TOK * (size_t)DIM];
__device__ __align__(16) __nv_bfloat16 g_cbh[KCB * DIM];

// ---------------- zero accumulators ----------------
__global__ void zero_kernel() {
    int t = blockIdx.x * blockDim.x + threadIdx.x;
    int stride = gridDim.x * blockDim.x;
    for (int i = t; i < KCB * DIM; i += stride) g_sums[i] = 0.0f;
    if (t < KCB) g_counts[t] = 0.0f;
}

// ---------------- c2/z2 + fused bf16 conversion ----------------
__global__ void c2_kernel(const float* __restrict__ cb) {
    int k = blockIdx.x, t = threadIdx.x;  // 128 threads
    float4 v = ((const float4*)(cb + (size_t)k * DIM))[t];
    union { __nv_bfloat162 h[2]; uint2 u; } cv;
    cv.h[0] = __floats2bfloat162_rn(v.x, v.y);
    cv.h[1] = __floats2bfloat162_rn(v.z, v.w);
    ((uint2*)(g_cbh + (size_t)k * DIM))[t] = cv.u;
    float s = v.x * v.x + v.y * v.y + v.z * v.z + v.w * v.w;
    #pragma unroll
    for (int o = 16; o > 0; o >>= 1) s += __shfl_down_sync(0xffffffffu, s, o);
    __shared__ float ws[4];
    if ((t & 31) == 0) ws[t >> 5] = s;
    __syncthreads();
    if (t == 0) g_c2[k] = ws[0] + ws[1] + ws[2] + ws[3];
}

__global__ void z2_kernel(const float* __restrict__ z) {
    int r = blockIdx.x, t = threadIdx.x;  // 128 threads
    float4 v = ((const float4*)(z + (size_t)r * DIM))[t];
    union { __nv_bfloat162 h[2]; uint2 u; } cv;
    cv.h[0] = __floats2bfloat162_rn(v.x, v.y);
    cv.h[1] = __floats2bfloat162_rn(v.z, v.w);
    ((uint2*)(g_zh + (size_t)r * DIM))[t] = cv.u;
    float s = v.x * v.x + v.y * v.y + v.z * v.z + v.w * v.w;
    #pragma unroll
    for (int o = 16; o > 0; o >>= 1) s += __shfl_down_sync(0xffffffffu, s, o);
    __shared__ float ws[4];
    if ((t & 31) == 0) ws[t >> 5] = s;
    __syncthreads();
    if (t == 0) g_z2[r] = ws[0] + ws[1] + ws[2] + ws[3];
}

// ---------------- fused HMMA GEMM + candidate select + exact rerank ------
// Per CTA: 128 rows, all 1024 codes (8 chunks of 128). Approx scores stay in
// smem. Scan runs on ALL 256 threads (thread = row x half-of-codes) with
// per-row smem atomic slot counters. Rerank = flattened (row,slot) worklist,
// exact reference arithmetic (sequential ascending-d fp32 FMA chain,
// fl(fl(z2-2dot)+c2)), per-row winner via atomicMin on packed (value,index)
// key -> lowest-index tie-break, identical decision rule to R4/R7.
#define PAW 72     // A/B smem pitch in bf16 (64 data + 8 pad)
#define PCW 132    // C smem pitch in f32 (128 rows + 4 pad)
#define OFF_A    0
#define OFF_B    18432
#define OFF_C    36864
#define OFF_C2   104448
#define OFF_MIN  104960
#define OFF_HMIN 105472
#define OFF_CNT  106496
#define OFF_CC   107008                    // cand codes [128][SLOTS]
#define OFF_CS   (OFF_CC + 128*SLOTS*4)    // cand scores [128][SLOTS]
#define OFF_BEST (OFF_CS + 128*SLOTS*4)    // u64 best key per row
#define OFF_OFL  (OFF_BEST + 128*8)        // overflow count + row list
#define GSM_SIZE (OFF_OFL + 4 + 128*4 + 16)

__device__ __forceinline__ unsigned long long packkey(float s, int k) {
    unsigned b = __float_as_uint(s);
    b = (b & 0x80000000u) ? ~b : (b | 0x80000000u);
    return ((unsigned long long)b << 32) | (unsigned)k;
}

__global__ __launch_bounds__(256, 1)
void gemm_kernel(const float* __restrict__ z, const float* __restrict__ cb) {
    extern __shared__ __align__(16) unsigned char sm[];
    __nv_bfloat16* As = (__nv_bfloat16*)(sm + OFF_A);   // [128][PAW]
    __nv_bfloat16* Bs = (__nv_bfloat16*)(sm + OFF_B);   // [128][PAW]
    float* Cs   = (float*)(sm + OFF_C);                 // [128 codes][PCW]
    float* c2s  = (float*)(sm + OFF_C2);                // [128]
    float* rmin = (float*)(sm + OFF_MIN);               // [128]
    float* hmin = (float*)(sm + OFF_HMIN);              // [256]
    int*   rcnt = (int*)(sm + OFF_CNT);                 // [128]
    int*   cc   = (int*)(sm + OFF_CC);                  // [128][SLOTS]
    float* cs   = (float*)(sm + OFF_CS);                // [128][SLOTS]
    unsigned long long* rbest = (unsigned long long*)(sm + OFF_BEST);
    int*   ofl  = (int*)(sm + OFF_OFL);                 // [0]=count, rows...

    const int tid = threadIdx.x;
    const int wid = tid >> 5;
    const int wr = wid & 3;    // row group: rows wr*32
    const int wc = wid >> 2;   // col group: codes wc*64
    const int rb = blockIdx.x * 128;
    const int sr = tid & 127;  // scan row
    const int sh = tid >> 7;   // scan half (codes sh*64..sh*64+63)

    if (tid < 128) { rmin[tid] = 3.4e38f; rcnt[tid] = 0; rbest[tid] = ~0ull; }
    if (tid == 0) ofl[0] = 0;

    wmma::fragment<wmma::matrix_a, 16, 16, 16, __nv_bfloat16, wmma::row_major> af[2];
    wmma::fragment<wmma::matrix_b, 16, 16, 16, __nv_bfloat16, wmma::col_major> bf[4];
    wmma::fragment<wmma::accumulator, 16, 16, 16, float> acc[2][4];

    for (int ch = 0; ch < 8; ch++) {
        if (tid < 128) c2s[tid] = g_c2[ch * 128 + tid];
        #pragma unroll
        for (int f = 0; f < 2; f++)
            #pragma unroll
            for (int g = 0; g < 4; g++)
                wmma::fill_fragment(acc[f][g], 0.0f);

        for (int slab = 0; slab < 8; slab++) {
            #pragma unroll
            for (int i = 0; i < 4; i++) {
                int idx = i * 256 + tid;           // 0..1023
                int r = idx >> 3, grp = idx & 7;
                *(uint4*)(As + r * PAW + grp * 8) =
                    *(const uint4*)(g_zh + (size_t)(rb + r) * DIM + slab * 64 + grp * 8);
            }
            #pragma unroll
            for (int i = 0; i < 4; i++) {
                int idx = i * 256 + tid;
                int n = idx >> 3, grp = idx & 7;
                *(uint4*)(Bs + n * PAW + grp * 8) =
                    *(const uint4*)(g_cbh + (size_t)(ch * 128 + n) * DIM + slab * 64 + grp * 8);
            }
            __syncthreads();

            #pragma unroll
            for (int ks = 0; ks < 4; ks++) {
                #pragma unroll
                for (int f = 0; f < 2; f++)
                    wmma::load_matrix_sync(af[f],
                        As + (wr * 32 + f * 16) * PAW + ks * 16, PAW);
                #pragma unroll
                for (int g = 0; g < 4; g++)
                    wmma::load_matrix_sync(bf[g],
                        Bs + (wc * 64 + g * 16) * PAW + ks * 16, PAW);
                #pragma unroll
                for (int f = 0; f < 2; f++)
                    #pragma unroll
                    for (int g = 0; g < 4; g++)
                        wmma::mma_sync(acc[f][g], af[f], bf[g], acc[f][g]);
            }
            __syncthreads();
        }

        // scores to smem, col-major: (row r, code c) -> Cs[c*PCW + r]
        #pragma unroll
        for (int f = 0; f < 2; f++)
            #pragma unroll
            for (int g = 0; g < 4; g++)
                wmma::store_matrix_sync(
                    Cs + (wc * 64 + g * 16) * PCW + wr * 32 + f * 16,
                    acc[f][g], PCW, wmma::mem_col_major);
        __syncthreads();

        // chunk scan, all 256 threads: per-(row,half) min over 64 codes
        {
            float m0 = 3.4e38f, m1 = 3.4e38f;   // two chains for ILP
            #pragma unroll 8
            for (int c = 0; c < 64; c += 2) {
                int c0 = sh * 64 + c;
                m0 = fminf(m0, fmaf(-2.0f, Cs[c0 * PCW + sr], c2s[c0]));
                m1 = fminf(m1, fmaf(-2.0f, Cs[(c0 + 1) * PCW + sr], c2s[c0 + 1]));
            }
            hmin[tid] = fminf(m0, m1);
        }
        __syncthreads();
        if (tid < 128)
            rmin[tid] = fminf(rmin[tid], fminf(hmin[tid], hmin[tid + 128]));
        __syncthreads();
        {
            float thr = rmin[sr] + MARGIN;
            #pragma unroll 4
            for (int c = 0; c < 64; c++) {
                int c0 = sh * 64 + c;
                float sc = fmaf(-2.0f, Cs[c0 * PCW + sr], c2s[c0]);
                if (sc <= thr) {
                    int slot = atomicAdd(&rcnt[sr], 1);
                    if (slot < SLOTS) {
                        cc[sr * SLOTS + slot] = ch * 128 + c0;
                        cs[sr * SLOTS + slot] = sc;
                    }
                }
            }
        }
        __syncthreads();
    }

    // ---- exact rerank: flattened (row, slot) worklist over 256 threads ----
    for (int i = tid; i < 128 * SLOTS; i += 256) {
        int r = i / SLOTS;
        int s = i - r * SLOTS;
        int cnt = rcnt[r];
        if (cnt > SLOTS || s >= cnt) continue;
        if (cs[i] > rmin[r] + MARGIN) continue;   // final-threshold filter
        int code = cc[i];
        const float* zr = z + (size_t)(rb + r) * DIM;
        const float* cr = cb + (size_t)code * DIM;
        float dot = 0.0f;
        #pragma unroll 8
        for (int d = 0; d < DIM; d++) dot = fmaf(zr[d], cr[d], dot);
        float t = fmaf(-2.0f, dot, g_z2[rb + r]);
        float sc = __fadd_rn(t, g_c2[code]);
        atomicMin(&rbest[r], packkey(sc, code));
    }
    __syncthreads();
    if (tid < 128) {
        if (rcnt[tid] <= SLOTS)
            g_idx[rb + tid] = (int)(rbest[tid] & 0xffffffffull);
        else {
            int slot = atomicAdd(&ofl[0], 1);
            ofl[1 + slot] = tid;
        }
    }
    __syncthreads();

    // ---- overflow fallback (prob ~0): block-cooperative exact full scan ----
    int novl = ofl[0];
    for (int i = 0; i < novl; i++) {
        int r = ofl[1 + i];
        float z2v = g_z2[rb + r];
        const float* zr = z + (size_t)(rb + r) * DIM;
        unsigned long long mykey = ~0ull;
        for (int code = tid; code < KCB; code += 256) {
            const float* cr = cb + (size_t)code * DIM;
            float dot = 0.0f;
            #pragma unroll 8
            for (int d = 0; d < DIM; d++) dot = fmaf(zr[d], cr[d], dot);
            float t = fmaf(-2.0f, dot, z2v);
            float sc = __fadd_rn(t, g_c2[code]);
            unsigned long long key = packkey(sc, code);
            if (key < mykey) mykey = key;
        }
        unsigned long long* kred = (unsigned long long*)Cs;
        kred[tid] = mykey;
        __syncthreads();
        if (tid == 0) {
            unsigned long long m = kred[0];
            for (int x = 1; x < 256; x++) if (kred[x] < m) m = kred[x];
            g_idx[rb + r] = (int)(m & 0xffffffffull);
        }
        __syncthreads();
    }
}

// ---------------- scatter: counts[k] += 1, sums[k] += z_n ----------------
__global__ void scatter_kernel(const float* __restrict__ z) {
    int g = blockIdx.x * blockDim.x + threadIdx.x;
    int row = g >> 5;
    int lane = g & 31;
    if (row >= N_TOK) return;
    int k = g_idx[row];
    const float4* zr = (const float4*)(z + (size_t)row * DIM);
    float* dst = g_sums + (size_t)k * DIM;
    #pragma unroll
    for (int i = 0; i < 4; i++) {
        int e = lane + i * 32;
        float4 v = zr[e];
        atomicAdd(dst + 4 * e + 0, v.x);
        atomicAdd(dst + 4 * e + 1, v.y);
        atomicAdd(dst + 4 * e + 2, v.z);
        atomicAdd(dst + 4 * e + 3, v.w);
    }
    if (lane == 0) atomicAdd(&g_counts[k], 1.0f);
}

// ---------------- EMA cluster sizes + total n ----------------
__global__ void newcs_kernel(const float* __restrict__ ema_cs) {
    __shared__ float red[1024];
    int t = threadIdx.x;  // 1024 threads
    float v = DECAY * ema_cs[t] + OMD * g_counts[t];
    g_newcs[t] = v;
    red[t] = v;
    __syncthreads();
    for (int s = 512; s > 0; s >>= 1) {
        if (t < s) red[t] += red[t + s];
        __syncthreads();
    }
    if (t == 0) g_ntot = red[0];
}

// ---------------- normalized codebook ----------------
__global__ void norm_kernel(const float* __restrict__ ema_w) {
    int k = blockIdx.x;
    int t = threadIdx.x;  // 128 threads
    float n = g_ntot;
    float cs = g_newcs[k];
    float smoothed = (cs + EPS_C) / (n + (float)KCB * EPS_C) * n;
    float inv = 1.0f / smoothed;
    const float4* w = (const float4*)(ema_w + (size_t)k * DIM);
    const float4* s = (const float4*)(g_sums + (size_t)k * DIM);
    float4* o = (float4*)(g_norm + (size_t)k * DIM);
    float4 wv = w[t], sv = s[t], ov;
    ov.x = (DECAY * wv.x + OMD * sv.x) * inv;
    ov.y = (DECAY * wv.y + OMD * sv.y) * inv;
    ov.z = (DECAY * wv.z + OMD * sv.z) * inv;
    ov.w = (DECAY * wv.w + OMD * sv.w) * inv;
    o[t] = ov;
}

// ---------------- gather + emit outputs ----------------
__global__ void out_kernel(const float* __restrict__ z,
                           float* __restrict__ idx_out,
                           float* __restrict__ q_out,
                           float* __restrict__ st_out) {
    int row = blockIdx.x;
    int t = threadIdx.x;  // 128 threads
    int k = g_idx[row];
    const float4* nr = (const float4*)(g_norm + (size_t)k * DIM);
    float4 qv = nr[t];
    if (q_out)
        ((float4*)(q_out + (size_t)row * DIM))[t] = qv;
    if (st_out) {
        const float4* zr = (const float4*)(z + (size_t)row * DIM);
        float4 zv = zr[t];
        float4 sv;
        sv.x = zv.x + (qv.x - zv.x);
        sv.y = zv.y + (qv.y - zv.y);
        sv.z = zv.z + (qv.z - zv.z);
        sv.w = zv.w + (qv.w - zv.w);
        ((float4*)(st_out + (size_t)row * DIM))[t] = sv;
    }
    if (idx_out && t == 0) idx_out[row] = (float)k;
}

// ---------------- host launcher ----------------
extern "C" void kernel_launch(void* const* d_in, const int* in_sizes, int n_in,
                              void* d_out, int out_size) {
    const float* z   = (const float*)d_in[0];
    const float* cb  = (const float*)d_in[1];
    const float* ecs = (const float*)d_in[2];
    const float* ew  = (const float*)d_in[3];
    float* out = (float*)d_out;

    static bool attr_set = false;
    if (!attr_set) {
        cudaFuncSetAttribute(gemm_kernel,
                             cudaFuncAttributeMaxDynamicSharedMemorySize,
                             GSM_SIZE);
        attr_set = true;
    }

    zero_kernel<<<512, 256>>>();
    c2_kernel<<<KCB, 128>>>(cb);
    z2_kernel<<<N_TOK, 128>>>(z);
    gemm_kernel<<<N_TOK / 128, 256, GSM_SIZE>>>(z, cb);
    scatter_kernel<<<(N_TOK * 32) / 256, 256>>>(z);
    newcs_kernel<<<1, 1024>>>(ecs);
    norm_kernel<<<KCB, 128>>>(ew);

    const long long N = N_TOK, D = DIM;
    const long long os = out_size;
    float *idxp = nullptr, *qp = nullptr, *stp = nullptr;
    if (os == N * (2 * D + 1)) {            // [idx, q, q_st]
        idxp = out; qp = out + N; stp = out + N + N * D;
    } else if (os == N * 2 * D) {           // [q, q_st]
        qp = out; stp = out + N * D;
    } else if (os == N * D) {               // [q]
        qp = out;
    } else if (os == N) {                   // [idx]
        idxp = out;
    } else {
        idxp = out;
        if (os >= N + N * D) qp = out + N;
        if (os >= N + 2 * N * D) stp = out + N + N * D;
    }
    out_kernel<<<N_TOK, 128>>>(z, idxp, qp, stp);
}